// round 2
// baseline (speedup 1.0000x reference)
#include <cuda_runtime.h>
#include <math.h>

#define BB   32
#define SS   4096
#define ENCD 512
#define ATTD 512

// Scratch (no allocations allowed in kernel_launch)
__device__ float g_q[BB * ATTD];        // 64 KB
__device__ float g_scores[BB * SS];     // 512 KB

// ---------------------------------------------------------------------------
// Kernel 0: q[b,a] = sum_e h[b,e] * W_h[e,a]
// ---------------------------------------------------------------------------
__global__ void query_kernel(const float* __restrict__ h,
                             const float* __restrict__ W_h) {
    const int b = blockIdx.x;
    const int a = threadIdx.x;      // 512 threads
    __shared__ float hs[512];
    hs[a] = h[b * 512 + a];
    __syncthreads();
    float acc = 0.f;
#pragma unroll 8
    for (int e = 0; e < 512; e++)
        acc = fmaf(hs[e], W_h[e * 512 + a], acc);
    g_q[b * 512 + a] = acc;
}

// ---------------------------------------------------------------------------
// Kernel 1: fused  key = enc @ W_s ; energy = tanh(q + key) ;
//                  score = v . energy ; mask
// Block = (batch b, 64-token tile). 256 threads.
// Thread (tm = t/16, tn = t%16): owns tokens [tm*4, tm*4+4) and, per N-half,
// columns { nbase + j*64 + tn*4 + k : j in 0..3, k in 0..3 }  (16 cols/half).
// ---------------------------------------------------------------------------
__global__ __launch_bounds__(256, 2)
void score_kernel(const float* __restrict__ enc_out,
                  const int* __restrict__ mask,
                  const float* __restrict__ W_s,
                  const float* __restrict__ v) {
    const int b  = blockIdx.y;
    const int s0 = blockIdx.x * 64;
    const int t  = threadIdx.x;
    const int tm = t >> 4;   // 0..15
    const int tn = t & 15;   // 0..15

    __shared__ float enc_s[64][36];    // 64 tokens x 32 e-dims (+pad)
    __shared__ float w_s[32][256];     // 32 e-dims  x 256 a-cols

    const float* encb = enc_out + ((long)b * SS + s0) * 512;

    float part[4] = {0.f, 0.f, 0.f, 0.f};

    for (int nh = 0; nh < 2; nh++) {
        const int nbase = nh * 256;

        float acc[4][4][4];
#pragma unroll
        for (int i = 0; i < 4; i++)
#pragma unroll
            for (int j = 0; j < 4; j++)
#pragma unroll
                for (int k = 0; k < 4; k++) acc[i][j][k] = 0.f;

        for (int kt = 0; kt < 16; kt++) {
            const int e0 = kt * 32;
            // enc tile: 64 rows x 32 cols = 512 float4, 2 per thread
#pragma unroll
            for (int i = 0; i < 2; i++) {
                int lin = t + i * 256;
                int r = lin >> 3;
                int c4 = lin & 7;
                float4 val = *(const float4*)(encb + (long)r * 512 + e0 + c4 * 4);
                *(float4*)&enc_s[r][c4 * 4] = val;
            }
            // W tile: 32 rows x 256 cols = 2048 float4, 8 per thread
#pragma unroll
            for (int i = 0; i < 8; i++) {
                int lin = t + i * 256;
                int r = lin >> 6;
                int c4 = lin & 63;
                float4 val = *(const float4*)(W_s + (long)(e0 + r) * 512 + nbase + c4 * 4);
                *(float4*)&w_s[r][c4 * 4] = val;
            }
            __syncthreads();

#pragma unroll
            for (int e = 0; e < 32; e++) {
                float4 wv[4];
#pragma unroll
                for (int j = 0; j < 4; j++)
                    wv[j] = *(const float4*)&w_s[e][j * 64 + tn * 4];
#pragma unroll
                for (int i = 0; i < 4; i++) {
                    float ev = enc_s[tm * 4 + i][e];
#pragma unroll
                    for (int j = 0; j < 4; j++) {
                        acc[i][j][0] = fmaf(ev, wv[j].x, acc[i][j][0]);
                        acc[i][j][1] = fmaf(ev, wv[j].y, acc[i][j][1]);
                        acc[i][j][2] = fmaf(ev, wv[j].z, acc[i][j][2]);
                        acc[i][j][3] = fmaf(ev, wv[j].w, acc[i][j][3]);
                    }
                }
            }
            __syncthreads();
        }

        // epilogue for this N-half: part += v * tanh(q + key)
#pragma unroll
        for (int j = 0; j < 4; j++) {
            const int c = nbase + j * 64 + tn * 4;
            float4 qv = *(const float4*)(g_q + b * 512 + c);
            float4 vv = *(const float4*)(v + c);
#pragma unroll
            for (int i = 0; i < 4; i++) {
                part[i] += vv.x * tanhf(qv.x + acc[i][j][0]);
                part[i] += vv.y * tanhf(qv.y + acc[i][j][1]);
                part[i] += vv.z * tanhf(qv.z + acc[i][j][2]);
                part[i] += vv.w * tanhf(qv.w + acc[i][j][3]);
            }
        }
    }

    // reduce over the 16 tn-threads (consecutive lanes, width-16 segments)
#pragma unroll
    for (int i = 0; i < 4; i++) {
        float p = part[i];
        p += __shfl_down_sync(0xffffffffu, p, 8, 16);
        p += __shfl_down_sync(0xffffffffu, p, 4, 16);
        p += __shfl_down_sync(0xffffffffu, p, 2, 16);
        p += __shfl_down_sync(0xffffffffu, p, 1, 16);
        if (tn == 0) {
            int s = s0 + tm * 4 + i;
            float sc = (mask[b * SS + s] != 0) ? -1e9f : p;
            g_scores[b * SS + s] = sc;
        }
    }
}

// ---------------------------------------------------------------------------
// Kernel 2: softmax over S per batch row; writes attn into output buffer
// ---------------------------------------------------------------------------
__global__ void softmax_kernel(float* __restrict__ out_attn) {
    const int b = blockIdx.x;
    const int t = threadIdx.x;   // 256
    __shared__ float red[256];
    const float* sc = g_scores + b * SS;

    float vals[16];
    float m = -INFINITY;
#pragma unroll
    for (int i = 0; i < 16; i++) {
        vals[i] = sc[t + i * 256];
        m = fmaxf(m, vals[i]);
    }
    red[t] = m;
    __syncthreads();
    for (int o = 128; o > 0; o >>= 1) {
        if (t < o) red[t] = fmaxf(red[t], red[t + o]);
        __syncthreads();
    }
    m = red[0];
    __syncthreads();

    float sum = 0.f;
#pragma unroll
    for (int i = 0; i < 16; i++) {
        vals[i] = expf(vals[i] - m);
        sum += vals[i];
    }
    red[t] = sum;
    __syncthreads();
    for (int o = 128; o > 0; o >>= 1) {
        if (t < o) red[t] += red[t + o];
        __syncthreads();
    }
    const float inv = 1.f / red[0];
#pragma unroll
    for (int i = 0; i < 16; i++)
        out_attn[b * SS + t + i * 256] = vals[i] * inv;
}

// ---------------------------------------------------------------------------
// Kernel 3: ctx[b,e] = sum_s attn[b,s] * enc[b,s,e]  (atomic partial sums)
// grid (4 e-chunks, 4 s-chunks, 32 b), 128 threads
// ---------------------------------------------------------------------------
__global__ void ctx_kernel(const float* __restrict__ enc_out,
                           const float* __restrict__ attn,
                           float* __restrict__ ctx) {
    const int b = blockIdx.z;
    const int e = blockIdx.x * 128 + threadIdx.x;
    const int sch = blockIdx.y;
    const float* ep = enc_out + ((long)b * SS + sch * 1024) * 512 + e;
    const float* ap = attn + b * SS + sch * 1024;

    float a0 = 0.f, a1 = 0.f, a2 = 0.f, a3 = 0.f;
#pragma unroll 4
    for (int s = 0; s < 1024; s += 4) {
        a0 = fmaf(ap[s + 0], ep[(long)(s + 0) * 512], a0);
        a1 = fmaf(ap[s + 1], ep[(long)(s + 1) * 512], a1);
        a2 = fmaf(ap[s + 2], ep[(long)(s + 2) * 512], a2);
        a3 = fmaf(ap[s + 3], ep[(long)(s + 3) * 512], a3);
    }
    atomicAdd(&ctx[b * 512 + e], (a0 + a1) + (a2 + a3));
}

// ---------------------------------------------------------------------------
extern "C" void kernel_launch(void* const* d_in, const int* in_sizes, int n_in,
                              void* d_out, int out_size) {
    const float* h    = (const float*)d_in[0];
    const float* enc  = (const float*)d_in[1];
    const int*   mask = (const int*)d_in[2];
    const float* W_h  = (const float*)d_in[3];
    const float* W_s  = (const float*)d_in[4];
    const float* v    = (const float*)d_in[5];

    float* out  = (float*)d_out;
    float* ctx  = out;                   // [32, 512]
    float* attn = out + BB * ATTD;       // [32, 4096]

    cudaMemsetAsync(ctx, 0, BB * ATTD * sizeof(float));
    query_kernel<<<BB, 512>>>(h, W_h);
    score_kernel<<<dim3(SS / 64, BB), 256>>>(enc, mask, W_s, v);
    softmax_kernel<<<BB, 256>>>(attn);
    ctx_kernel<<<dim3(4, 4, BB), 128>>>(enc, attn, ctx);
}

// round 4
// speedup vs baseline: 2.0718x; 2.0718x over previous
#include <cuda_runtime.h>
#include <cuda_bf16.h>
#include <math.h>
#include <stdint.h>

#define BB 32
#define SS 4096

// ---------------- device scratch ----------------
__device__ float g_q[BB * 512];
__device__ float g_scores[BB * SS];
__device__ __align__(16) unsigned short g_Wt_hi[512 * 512];  // W^T [a][e], bf16 hi
__device__ __align__(16) unsigned short g_Wt_lo[512 * 512];  // W^T [a][e], bf16 lo

// ---------------- smem layout (dynamic) ----------------
#define OFF_AHI 0          // 64 rows x 1024B
#define OFF_ALO 65536      // 64 rows x 1024B
#define OFF_B   131072     // 2 bufs x (hi 8KB + lo 8KB) = 32KB
#define OFF_Q   163840     // 512 f32
#define OFF_V   165888     // 512 f32
#define OFF_RED 167936     // 2x64 f32
#define SMEM_DYN 168448

// ---------------- asm helpers ----------------
__device__ __forceinline__ uint32_t smem_to_u32(const void* p) {
    uint32_t a;
    asm("{ .reg .u64 t; cvta.to.shared.u64 t, %1; cvt.u32.u64 %0, t; }" : "=r"(a) : "l"(p));
    return a;
}
__device__ __forceinline__ void ldsm4(uint32_t* r, uint32_t addr) {
    asm volatile("ldmatrix.sync.aligned.m8n8.x4.shared.b16 {%0,%1,%2,%3}, [%4];"
                 : "=r"(r[0]), "=r"(r[1]), "=r"(r[2]), "=r"(r[3]) : "r"(addr));
}
__device__ __forceinline__ void mma16816(float* c, const uint32_t* a, uint32_t b0, uint32_t b1) {
    asm volatile("mma.sync.aligned.m16n8k16.row.col.f32.bf16.bf16.f32 "
                 "{%0,%1,%2,%3}, {%4,%5,%6,%7}, {%8,%9}, {%0,%1,%2,%3};"
                 : "+f"(c[0]), "+f"(c[1]), "+f"(c[2]), "+f"(c[3])
                 : "r"(a[0]), "r"(a[1]), "r"(a[2]), "r"(a[3]), "r"(b0), "r"(b1));
}
__device__ __forceinline__ void cp_async16(uint32_t dst, const void* src) {
    asm volatile("{ .reg .u64 g; cvta.to.global.u64 g, %1; "
                 "cp.async.cg.shared.global [%0], [g], 16; }"
                 :: "r"(dst), "l"(src) : "memory");
}
#define CP_COMMIT() asm volatile("cp.async.commit_group;" ::: "memory")
#define CP_WAIT0()  asm volatile("cp.async.wait_group 0;" ::: "memory")

// FMA-only tanh (no MUFU): exp2 via magic-rint + deg-5 poly, Newton reciprocal.
__device__ __forceinline__ float fast_tanh(float x) {
    float z = x * 2.885390081777927f;            // 2x * log2(e)
    z = fminf(fmaxf(z, -30.f), 30.f);
    float tt = z + 12582912.0f;                  // 1.5*2^23: round-to-nearest
    int   ib = __float_as_int(tt) - 0x4B400000;  // = rint(z)
    float r  = z - (tt - 12582912.0f);           // r in [-0.5, 0.5]
    float p = 1.3333558e-3f;
    p = fmaf(p, r, 9.6181291e-3f);
    p = fmaf(p, r, 5.5504109e-2f);
    p = fmaf(p, r, 2.4022651e-1f);
    p = fmaf(p, r, 6.9314718e-1f);
    p = fmaf(p, r, 1.0f);
    float E = __int_as_float((ib + 127) << 23) * p;   // e^{2x}
    float d = E + 1.0f;
    float y = __int_as_float(0x7EF311C3 - __float_as_int(d));
    y = y * fmaf(-d, y, 2.0f);
    y = y * fmaf(-d, y, 2.0f);
    y = y * fmaf(-d, y, 2.0f);
    return (E - 1.0f) * y;
}

// ---------------------------------------------------------------------------
// Prep: W_t_{hi,lo}[a, e] = split(W_s[e, a])
// ---------------------------------------------------------------------------
__global__ void wsplit_kernel(const float* __restrict__ W_s) {
    int e = blockIdx.x;
    int a = threadIdx.x;
    float w = W_s[e * 512 + a];
    uint32_t u = __float_as_uint(w);
    g_Wt_hi[(size_t)a * 512 + e] = (unsigned short)(u >> 16);
    float lo = w - __uint_as_float(u & 0xffff0000u);
    __nv_bfloat16 lb = __float2bfloat16(lo);
    g_Wt_lo[(size_t)a * 512 + e] = *(unsigned short*)&lb;
}

// ---------------------------------------------------------------------------
// Kernel 0: q[b,a] = sum_e h[b,e] * W_h[e,a]
// ---------------------------------------------------------------------------
__global__ void query_kernel(const float* __restrict__ h,
                             const float* __restrict__ W_h) {
    const int b = blockIdx.x;
    const int a = threadIdx.x;
    __shared__ float hs[512];
    hs[a] = h[b * 512 + a];
    __syncthreads();
    float acc = 0.f;
#pragma unroll 8
    for (int e = 0; e < 512; e++)
        acc = fmaf(hs[e], W_h[e * 512 + a], acc);
    g_q[b * 512 + a] = acc;
}

// ---------------------------------------------------------------------------
// Score kernel (HMMA mma.sync, 3-pass bf16 split):
//   per CTA one (b, 64-token tile); D = enc64x512 @ W512x512; score = v.tanh(q+D)
// ---------------------------------------------------------------------------
__device__ __forceinline__ void issue_B(uint32_t sb, int s, int buf, int t) {
    const int nc = s >> 3, ks = s & 7;
    const int n0 = nc << 6, k0 = ks << 6;
    const uint32_t bh = sb + OFF_B + buf * 16384;
#pragma unroll
    for (int qq = 0; qq < 2; qq++) {
        int lin = t + qq * 256;
        int n = lin >> 3, cc = lin & 7;
        uint32_t dst = (uint32_t)n * 128 + (uint32_t)((cc ^ (n & 7)) << 4);
        const unsigned short* sh = g_Wt_hi + (size_t)(n0 + n) * 512 + k0 + cc * 8;
        const unsigned short* sl = g_Wt_lo + (size_t)(n0 + n) * 512 + k0 + cc * 8;
        cp_async16(bh + dst, sh);
        cp_async16(bh + 8192 + dst, sl);
    }
}

__global__ __launch_bounds__(256, 1)
void score_mma_kernel(const float* __restrict__ enc,
                      const int* __restrict__ mask,
                      const float* __restrict__ v) {
    extern __shared__ __align__(128) char sm[];
    const uint32_t sb = smem_to_u32(sm);
    const int t = threadIdx.x;
    const int w = t >> 5, lid = t & 31;
    const int tile = blockIdx.x;   // 0..63 (64-token tiles)
    const int b = blockIdx.y;      // 0..31
    const int mw = w & 3;          // M-warp: tokens mw*16..+16
    const int nw = w >> 2;         // N-warp: cols  nw*32..+32 within chunk

    // stage q, v
    float* sq = (float*)(sm + OFF_Q);
    float* sv = (float*)(sm + OFF_V);
    for (int i = t; i < 512; i += 256) { sq[i] = g_q[b * 512 + i]; sv[i] = v[i]; }

    const float* encb = enc + ((size_t)b * SS + (size_t)tile * 64) * 512;

    // prefetch B stage 0
    issue_B(sb, 0, 0, t);
    CP_COMMIT();

    // A: enc [64 x 512] fp32 -> bf16 hi/lo, resident, swizzled
#pragma unroll 1
    for (int i = 0; i < 16; i++) {
        int lin = t + i * 256;
        int m = lin >> 6, c = lin & 63;
        const float* p = encb + (size_t)m * 512 + c * 8;
        float4 f0 = *(const float4*)p;
        float4 f1 = *(const float4*)(p + 4);
        uint32_t x0 = __float_as_uint(f0.x), x1 = __float_as_uint(f0.y);
        uint32_t x2 = __float_as_uint(f0.z), x3 = __float_as_uint(f0.w);
        uint32_t x4 = __float_as_uint(f1.x), x5 = __float_as_uint(f1.y);
        uint32_t x6 = __float_as_uint(f1.z), x7 = __float_as_uint(f1.w);
        uint4 hv;
        hv.x = __byte_perm(x0, x1, 0x7632);
        hv.y = __byte_perm(x2, x3, 0x7632);
        hv.z = __byte_perm(x4, x5, 0x7632);
        hv.w = __byte_perm(x6, x7, 0x7632);
        float l0 = f0.x - __uint_as_float(x0 & 0xffff0000u);
        float l1 = f0.y - __uint_as_float(x1 & 0xffff0000u);
        float l2 = f0.z - __uint_as_float(x2 & 0xffff0000u);
        float l3 = f0.w - __uint_as_float(x3 & 0xffff0000u);
        float l4 = f1.x - __uint_as_float(x4 & 0xffff0000u);
        float l5 = f1.y - __uint_as_float(x5 & 0xffff0000u);
        float l6 = f1.z - __uint_as_float(x6 & 0xffff0000u);
        float l7 = f1.w - __uint_as_float(x7 & 0xffff0000u);
        uint4 lv;
        asm("cvt.rn.satfinite.bf16x2.f32 %0, %1, %2;" : "=r"(lv.x) : "f"(l1), "f"(l0));
        asm("cvt.rn.satfinite.bf16x2.f32 %0, %1, %2;" : "=r"(lv.y) : "f"(l3), "f"(l2));
        asm("cvt.rn.satfinite.bf16x2.f32 %0, %1, %2;" : "=r"(lv.z) : "f"(l5), "f"(l4));
        asm("cvt.rn.satfinite.bf16x2.f32 %0, %1, %2;" : "=r"(lv.w) : "f"(l7), "f"(l6));
        uint32_t off = (uint32_t)m * 1024 + (uint32_t)((c ^ (m & 7)) << 4);
        *(uint4*)(sm + OFF_AHI + off) = hv;
        *(uint4*)(sm + OFF_ALO + off) = lv;
    }

    // per-thread ldmatrix address components
    const int rA = (mw << 4) + ((lid >> 3) & 1) * 8 + (lid & 7);   // 0..63
    const int cA_add = lid >> 4;                                    // 0/1
    const uint32_t aRowOff = (uint32_t)rA * 1024;
    const int rAx = rA & 7;
    const int rB0 = (nw << 5) + ((lid >> 4) & 1) * 8 + (lid & 7);   // p=0 frag pair
    const int rB1 = rB0 + 16;                                       // p=1 frag pair
    const int cB_add = (lid >> 3) & 1;
    const uint32_t bRow0 = (uint32_t)rB0 * 128;
    const uint32_t bRow1 = (uint32_t)rB1 * 128;
    const int rB0x = rB0 & 7, rB1x = rB1 & 7;

    float part0 = 0.f, part1 = 0.f;
    float acc[4][4];
    int buf = 0;

#pragma unroll 1
    for (int s = 0; s < 64; s++) {
        const int nc = s >> 3, ks = s & 7;
        CP_WAIT0();
        __syncthreads();
        if (s + 1 < 64) { issue_B(sb, s + 1, buf ^ 1, t); CP_COMMIT(); }

        if (ks == 0) {
#pragma unroll
            for (int j = 0; j < 4; j++)
#pragma unroll
                for (int e = 0; e < 4; e++) acc[j][e] = 0.f;
        }

        const uint32_t bhb = sb + OFF_B + buf * 16384;
        const uint32_t blb = bhb + 8192;

#pragma unroll
        for (int kk = 0; kk < 4; kk++) {
            const int cA = ks * 8 + kk * 2 + cA_add;
            uint32_t ah[4], al[4];
            uint32_t aoff = aRowOff + (uint32_t)((cA ^ rAx) << 4);
            ldsm4(ah, sb + OFF_AHI + aoff);
            ldsm4(al, sb + OFF_ALO + aoff);

            const int cB = kk * 2 + cB_add;
            uint32_t bh0[4], bh1[4], bl0[4], bl1[4];
            const uint32_t off0 = bRow0 + (uint32_t)((cB ^ rB0x) << 4);
            const uint32_t off1 = bRow1 + (uint32_t)((cB ^ rB1x) << 4);
            ldsm4(bh0, bhb + off0);
            ldsm4(bh1, bhb + off1);
            ldsm4(bl0, blb + off0);
            ldsm4(bl1, blb + off1);

            // pass 1: Ah*Bh (4 independent chains)
            mma16816(acc[0], ah, bh0[0], bh0[1]);
            mma16816(acc[1], ah, bh0[2], bh0[3]);
            mma16816(acc[2], ah, bh1[0], bh1[1]);
            mma16816(acc[3], ah, bh1[2], bh1[3]);
            // pass 2: Ah*Bl
            mma16816(acc[0], ah, bl0[0], bl0[1]);
            mma16816(acc[1], ah, bl0[2], bl0[3]);
            mma16816(acc[2], ah, bl1[0], bl1[1]);
            mma16816(acc[3], ah, bl1[2], bl1[3]);
            // pass 3: Al*Bh
            mma16816(acc[0], al, bh0[0], bh0[1]);
            mma16816(acc[1], al, bh0[2], bh0[3]);
            mma16816(acc[2], al, bh1[0], bh1[1]);
            mma16816(acc[3], al, bh1[2], bh1[3]);
        }

        if (ks == 7) {
            const int cbase = nc * 64 + nw * 32 + 2 * (lid & 3);
#pragma unroll
            for (int j = 0; j < 4; j++) {
                const int c = cbase + j * 8;
                float2 q2 = *(const float2*)&sq[c];
                float2 v2 = *(const float2*)&sv[c];
                part0 += v2.x * fast_tanh(q2.x + acc[j][0]);
                part0 += v2.y * fast_tanh(q2.y + acc[j][1]);
                part1 += v2.x * fast_tanh(q2.x + acc[j][2]);
                part1 += v2.y * fast_tanh(q2.y + acc[j][3]);
            }
        }
        buf ^= 1;
    }

    // reduce over lane quads (same token), then across the 2 N-warps via smem
    part0 += __shfl_xor_sync(0xffffffffu, part0, 1);
    part0 += __shfl_xor_sync(0xffffffffu, part0, 2);
    part1 += __shfl_xor_sync(0xffffffffu, part1, 1);
    part1 += __shfl_xor_sync(0xffffffffu, part1, 2);

    float* red = (float*)(sm + OFF_RED);   // [2][64]
    __syncthreads();
    if ((lid & 3) == 0) {
        red[nw * 64 + mw * 16 + (lid >> 2)]     = part0;
        red[nw * 64 + mw * 16 + 8 + (lid >> 2)] = part1;
    }
    __syncthreads();
    if (t < 64) {
        float p = red[t] + red[64 + t];
        int sg = tile * 64 + t;
        g_scores[b * SS + sg] = (mask[b * SS + sg] != 0) ? -1e9f : p;
    }
}

// ---------------------------------------------------------------------------
// Kernel 2: softmax over S per batch row
// ---------------------------------------------------------------------------
__global__ void softmax_kernel(float* __restrict__ out_attn) {
    const int b = blockIdx.x;
    const int t = threadIdx.x;   // 256
    __shared__ float red[256];
    const float* sc = g_scores + b * SS;

    float vals[16];
    float m = -INFINITY;
#pragma unroll
    for (int i = 0; i < 16; i++) {
        vals[i] = sc[t + i * 256];
        m = fmaxf(m, vals[i]);
    }
    red[t] = m;
    __syncthreads();
    for (int o = 128; o > 0; o >>= 1) {
        if (t < o) red[t] = fmaxf(red[t], red[t + o]);
        __syncthreads();
    }
    m = red[0];
    __syncthreads();

    float sum = 0.f;
#pragma unroll
    for (int i = 0; i < 16; i++) {
        vals[i] = expf(vals[i] - m);
        sum += vals[i];
    }
    red[t] = sum;
    __syncthreads();
    for (int o = 128; o > 0; o >>= 1) {
        if (t < o) red[t] += red[t + o];
        __syncthreads();
    }
    const float inv = 1.f / red[0];
#pragma unroll
    for (int i = 0; i < 16; i++)
        out_attn[b * SS + t + i * 256] = vals[i] * inv;
}

// ---------------------------------------------------------------------------
// Kernel 3: ctx[b,e] = sum_s attn[b,s] * enc[b,s,e]
// grid (32 s-chunks, 32 b), 128 threads, float4 per thread
// ---------------------------------------------------------------------------
__global__ void ctx_kernel(const float* __restrict__ enc_out,
                           const float* __restrict__ attn,
                           float* __restrict__ ctx) {
    const int b = blockIdx.y;
    const int sch = blockIdx.x;
    const int e4 = threadIdx.x * 4;
    const float* ap = attn + b * SS + sch * 128;
    const float* ep = enc_out + ((size_t)b * SS + (size_t)sch * 128) * 512 + e4;

    float4 acc = make_float4(0.f, 0.f, 0.f, 0.f);
#pragma unroll 4
    for (int s = 0; s < 128; s++) {
        float a = __ldg(&ap[s]);
        float4 x = *(const float4*)(ep + (size_t)s * 512);
        acc.x = fmaf(a, x.x, acc.x);
        acc.y = fmaf(a, x.y, acc.y);
        acc.z = fmaf(a, x.z, acc.z);
        acc.w = fmaf(a, x.w, acc.w);
    }
    atomicAdd(&ctx[b * 512 + e4 + 0], acc.x);
    atomicAdd(&ctx[b * 512 + e4 + 1], acc.y);
    atomicAdd(&ctx[b * 512 + e4 + 2], acc.z);
    atomicAdd(&ctx[b * 512 + e4 + 3], acc.w);
}

// ---------------------------------------------------------------------------
extern "C" void kernel_launch(void* const* d_in, const int* in_sizes, int n_in,
                              void* d_out, int out_size) {
    const float* h    = (const float*)d_in[0];
    const float* enc  = (const float*)d_in[1];
    const int*   mask = (const int*)d_in[2];
    const float* W_h  = (const float*)d_in[3];
    const float* W_s  = (const float*)d_in[4];
    const float* v    = (const float*)d_in[5];

    float* out  = (float*)d_out;
    float* ctx  = out;                 // [32, 512]
    float* attn = out + BB * 512;      // [32, 4096]

    static int attr_done = 0;
    if (!attr_done) {
        cudaFuncSetAttribute(score_mma_kernel,
                             cudaFuncAttributeMaxDynamicSharedMemorySize, SMEM_DYN);
        attr_done = 1;
    }

    cudaMemsetAsync(ctx, 0, BB * 512 * sizeof(float));
    wsplit_kernel<<<512, 512>>>(W_s);
    query_kernel<<<BB, 512>>>(h, W_h);
    score_mma_kernel<<<dim3(64, 32), 256, SMEM_DYN>>>(enc, mask, v);
    softmax_kernel<<<BB, 256>>>(attn);
    ctx_kernel<<<dim3(32, 32), 128>>>(enc, attn, ctx);
}

// round 5
// speedup vs baseline: 2.7434x; 1.3242x over previous
#include <cuda_runtime.h>
#include <cuda_bf16.h>
#include <math.h>
#include <stdint.h>

#define BB 32
#define SS 4096

// ---------------- device scratch ----------------
__device__ float g_q[BB * 512];
__device__ float g_scores[BB * SS];
__device__ __align__(16) unsigned short g_Wt_hi[512 * 512];  // W^T [a][e], bf16 hi
__device__ __align__(16) unsigned short g_Wt_lo[512 * 512];  // W^T [a][e], bf16 lo

// ---------------- smem layout (dynamic) ----------------
// A: 2 bufs x (hi 16KB + lo 16KB) = 64KB   rows: 128 x 128B
// B: 2 bufs x (hi 32KB + lo 32KB) = 128KB  rows: 256 x 128B
#define OFF_A    0
#define OFF_B    65536
#define OFF_RED  196608   // 4 x 128 f32
#define SMEM_DYN 198656

// ---------------- asm helpers ----------------
__device__ __forceinline__ uint32_t smem_to_u32(const void* p) {
    uint32_t a;
    asm("{ .reg .u64 t; cvta.to.shared.u64 t, %1; cvt.u32.u64 %0, t; }" : "=r"(a) : "l"(p));
    return a;
}
__device__ __forceinline__ void ldsm4(uint32_t* r, uint32_t addr) {
    asm volatile("ldmatrix.sync.aligned.m8n8.x4.shared.b16 {%0,%1,%2,%3}, [%4];"
                 : "=r"(r[0]), "=r"(r[1]), "=r"(r[2]), "=r"(r[3]) : "r"(addr));
}
__device__ __forceinline__ void mma16816(float* c, const uint32_t* a, uint32_t b0, uint32_t b1) {
    asm volatile("mma.sync.aligned.m16n8k16.row.col.f32.bf16.bf16.f32 "
                 "{%0,%1,%2,%3}, {%4,%5,%6,%7}, {%8,%9}, {%0,%1,%2,%3};"
                 : "+f"(c[0]), "+f"(c[1]), "+f"(c[2]), "+f"(c[3])
                 : "r"(a[0]), "r"(a[1]), "r"(a[2]), "r"(a[3]), "r"(b0), "r"(b1));
}
__device__ __forceinline__ void cp_async16(uint32_t dst, const void* src) {
    asm volatile("{ .reg .u64 g; cvta.to.global.u64 g, %1; "
                 "cp.async.cg.shared.global [%0], [g], 16; }"
                 :: "r"(dst), "l"(src) : "memory");
}
#define CP_COMMIT() asm volatile("cp.async.commit_group;" ::: "memory")
#define CP_WAIT0()  asm volatile("cp.async.wait_group 0;" ::: "memory")

// FMA-only tanh (no MUFU)
__device__ __forceinline__ float fast_tanh(float x) {
    float z = x * 2.885390081777927f;
    z = fminf(fmaxf(z, -30.f), 30.f);
    float tt = z + 12582912.0f;
    int   ib = __float_as_int(tt) - 0x4B400000;
    float r  = z - (tt - 12582912.0f);
    float p = 1.3333558e-3f;
    p = fmaf(p, r, 9.6181291e-3f);
    p = fmaf(p, r, 5.5504109e-2f);
    p = fmaf(p, r, 2.4022651e-1f);
    p = fmaf(p, r, 6.9314718e-1f);
    p = fmaf(p, r, 1.0f);
    float E = __int_as_float((ib + 127) << 23) * p;
    float d = E + 1.0f;
    float y = __int_as_float(0x7EF311C3 - __float_as_int(d));
    y = y * fmaf(-d, y, 2.0f);
    y = y * fmaf(-d, y, 2.0f);
    y = y * fmaf(-d, y, 2.0f);
    return (E - 1.0f) * y;
}

// ---------------------------------------------------------------------------
__global__ void zero_scores_kernel() {
    ((float4*)g_scores)[blockIdx.x * 512 + threadIdx.x] =
        make_float4(0.f, 0.f, 0.f, 0.f);
}

// ---------------------------------------------------------------------------
// Prep: W_t_{hi,lo}[a, e] = split(W_s[e, a])
// ---------------------------------------------------------------------------
__global__ void wsplit_kernel(const float* __restrict__ W_s) {
    int e = blockIdx.x;
    int a = threadIdx.x;
    float w = W_s[e * 512 + a];
    uint32_t u = __float_as_uint(w);
    g_Wt_hi[(size_t)a * 512 + e] = (unsigned short)(u >> 16);
    float lo = w - __uint_as_float(u & 0xffff0000u);
    __nv_bfloat16 lb = __float2bfloat16(lo);
    g_Wt_lo[(size_t)a * 512 + e] = *(unsigned short*)&lb;
}

// ---------------------------------------------------------------------------
// Kernel 0: q[b,a] = sum_e h[b,e] * W_h[e,a]
// ---------------------------------------------------------------------------
__global__ void query_kernel(const float* __restrict__ h,
                             const float* __restrict__ W_h) {
    const int b = blockIdx.x;
    const int a = threadIdx.x;
    __shared__ float hs[512];
    hs[a] = h[b * 512 + a];
    __syncthreads();
    float acc = 0.f;
#pragma unroll 8
    for (int e = 0; e < 512; e++)
        acc = fmaf(hs[e], W_h[e * 512 + a], acc);
    g_q[b * 512 + a] = acc;
}

// ---------------------------------------------------------------------------
// Score kernel: CTA = (m-tile 128 tok, n-tile 256 attn, b). 512 thr, 16 warps.
// Warp (mw=w&3, nw=w>>2): tile m32 x n64. K streamed: 8 stages of 64.
// 3-pass bf16-split HMMA; epilogue v.tanh(q+D) once; atomicAdd partial scores.
// ---------------------------------------------------------------------------
__global__ __launch_bounds__(512, 1)
void score_mma_kernel(const float* __restrict__ enc,
                      const float* __restrict__ v) {
    extern __shared__ __align__(128) char sm[];
    const uint32_t sb = smem_to_u32(sm);
    const int t = threadIdx.x;
    const int w = t >> 5, lid = t & 31;
    const int mw = w & 3, nw = w >> 2;
    const int mtile = blockIdx.x;          // 0..31
    const int n0 = blockIdx.y * 256;       // 0 or 256
    const int b = blockIdx.z;

    const float* encb = enc + ((size_t)b * SS + (size_t)mtile * 128) * 512;

    float acc[2][8][4];
#pragma unroll
    for (int mg = 0; mg < 2; mg++)
#pragma unroll
        for (int j = 0; j < 8; j++)
#pragma unroll
            for (int e = 0; e < 4; e++) acc[mg][j][e] = 0.f;

    const int am = t >> 2, akq = t & 3;    // A-stage role of this thread

    // ---- stage helpers (inlined manually) --------------------------------
    // B issue for stage s into buf
#define ISSUE_B(s_, buf_) do {                                                \
    const uint32_t bb = sb + OFF_B + (buf_) * 65536;                          \
    const int k0_ = (s_) * 64;                                                \
    _Pragma("unroll")                                                         \
    for (int i_ = 0; i_ < 8; i_++) {                                          \
        int idx_ = t + i_ * 512;                                              \
        int half_ = idx_ >> 11;                                               \
        int r_ = (idx_ >> 3) & 255;                                           \
        int cc_ = idx_ & 7;                                                   \
        const unsigned short* src_ =                                          \
            (half_ ? g_Wt_lo : g_Wt_hi) + (size_t)(n0 + r_) * 512 + k0_ + cc_ * 8; \
        cp_async16(bb + half_ * 32768 + r_ * 128 + ((cc_ ^ (r_ & 7)) << 4), src_); \
    } } while (0)

#define LOAD_A(s_, af_) do {                                                  \
    const float* p_ = encb + (size_t)am * 512 + (s_) * 64 + akq * 16;         \
    af_[0] = *(const float4*)(p_);                                            \
    af_[1] = *(const float4*)(p_ + 4);                                        \
    af_[2] = *(const float4*)(p_ + 8);                                        \
    af_[3] = *(const float4*)(p_ + 12);                                       \
    } while (0)

#define STORE_A(buf_, af_) do {                                               \
    char* ab_ = sm + OFF_A + (buf_) * 32768;                                  \
    _Pragma("unroll")                                                         \
    for (int c_ = 0; c_ < 2; c_++) {                                          \
        float4 f0 = af_[2 * c_], f1 = af_[2 * c_ + 1];                        \
        uint32_t x0 = __float_as_uint(f0.x), x1 = __float_as_uint(f0.y);      \
        uint32_t x2 = __float_as_uint(f0.z), x3 = __float_as_uint(f0.w);      \
        uint32_t x4 = __float_as_uint(f1.x), x5 = __float_as_uint(f1.y);      \
        uint32_t x6 = __float_as_uint(f1.z), x7 = __float_as_uint(f1.w);      \
        uint4 hv;                                                             \
        hv.x = __byte_perm(x0, x1, 0x7632);                                   \
        hv.y = __byte_perm(x2, x3, 0x7632);                                   \
        hv.z = __byte_perm(x4, x5, 0x7632);                                   \
        hv.w = __byte_perm(x6, x7, 0x7632);                                   \
        float l0 = f0.x - __uint_as_float(x0 & 0xffff0000u);                  \
        float l1 = f0.y - __uint_as_float(x1 & 0xffff0000u);                  \
        float l2 = f0.z - __uint_as_float(x2 & 0xffff0000u);                  \
        float l3 = f0.w - __uint_as_float(x3 & 0xffff0000u);                  \
        float l4 = f1.x - __uint_as_float(x4 & 0xffff0000u);                  \
        float l5 = f1.y - __uint_as_float(x5 & 0xffff0000u);                  \
        float l6 = f1.z - __uint_as_float(x6 & 0xffff0000u);                  \
        float l7 = f1.w - __uint_as_float(x7 & 0xffff0000u);                  \
        uint4 lv;                                                             \
        asm("cvt.rn.satfinite.bf16x2.f32 %0, %1, %2;" : "=r"(lv.x) : "f"(l1), "f"(l0)); \
        asm("cvt.rn.satfinite.bf16x2.f32 %0, %1, %2;" : "=r"(lv.y) : "f"(l3), "f"(l2)); \
        asm("cvt.rn.satfinite.bf16x2.f32 %0, %1, %2;" : "=r"(lv.z) : "f"(l5), "f"(l4)); \
        asm("cvt.rn.satfinite.bf16x2.f32 %0, %1, %2;" : "=r"(lv.w) : "f"(l7), "f"(l6)); \
        int cc_ = akq * 2 + c_;                                               \
        uint32_t off_ = am * 128 + ((cc_ ^ (am & 7)) << 4);                   \
        *(uint4*)(ab_ + off_) = hv;                                           \
        *(uint4*)(ab_ + 16384 + off_) = lv;                                   \
    } } while (0)

    // ldsm address components
    const int rA = mw * 32 + ((lid >> 3) & 1) * 8 + (lid & 7);   // mg0 row
    const int rAx = rA & 7;
    const int cAadd = lid >> 4;
    const int rB = nw * 64 + ((lid >> 4) & 1) * 8 + (lid & 7);
    const int cBadd = (lid >> 3) & 1;

    // ---- prologue --------------------------------------------------------
    ISSUE_B(0, 0);
    CP_COMMIT();
    {
        float4 af[4];
        LOAD_A(0, af);
        STORE_A(0, af);
    }
    CP_WAIT0();
    __syncthreads();

    int buf = 0;
#pragma unroll 1
    for (int s = 0; s < 8; s++) {
        float4 af[4];
        if (s < 7) {
            ISSUE_B(s + 1, buf ^ 1);
            CP_COMMIT();
            LOAD_A(s + 1, af);
        }

        const uint32_t abh = sb + OFF_A + buf * 32768;
        const uint32_t abl = abh + 16384;
        const uint32_t bbh = sb + OFF_B + buf * 65536;
        const uint32_t bbl = bbh + 32768;

#pragma unroll
        for (int kk = 0; kk < 4; kk++) {
            const int cA = kk * 2 + cAadd;
            const uint32_t a0off = (uint32_t)rA * 128 + (uint32_t)((cA ^ rAx) << 4);
            const uint32_t a1off = a0off + 16 * 128;          // (rA+16)&7 == rA&7
            const int cB = kk * 2 + cBadd;
            uint32_t boff[4];
            uint32_t bm[4][4];
#pragma unroll
            for (int j = 0; j < 4; j++) {
                int r = rB + j * 16;
                boff[j] = (uint32_t)r * 128 + (uint32_t)((cB ^ (r & 7)) << 4);
                ldsm4(bm[j], bbh + boff[j]);
            }
            uint32_t ah0[4], ah1[4], al[4];
            ldsm4(ah0, abh + a0off);
            ldsm4(ah1, abh + a1off);

            // pass AhBh
#pragma unroll
            for (int j = 0; j < 4; j++) {
                mma16816(acc[0][2 * j],     ah0, bm[j][0], bm[j][1]);
                mma16816(acc[0][2 * j + 1], ah0, bm[j][2], bm[j][3]);
                mma16816(acc[1][2 * j],     ah1, bm[j][0], bm[j][1]);
                mma16816(acc[1][2 * j + 1], ah1, bm[j][2], bm[j][3]);
            }
            // pass AlBh (mg0 then mg1, reuse al regs)
            ldsm4(al, abl + a0off);
#pragma unroll
            for (int j = 0; j < 4; j++) {
                mma16816(acc[0][2 * j],     al, bm[j][0], bm[j][1]);
                mma16816(acc[0][2 * j + 1], al, bm[j][2], bm[j][3]);
            }
            ldsm4(al, abl + a1off);
#pragma unroll
            for (int j = 0; j < 4; j++) {
                mma16816(acc[1][2 * j],     al, bm[j][0], bm[j][1]);
                mma16816(acc[1][2 * j + 1], al, bm[j][2], bm[j][3]);
            }
            // pass AhBl (overwrite bm with B-lo)
#pragma unroll
            for (int j = 0; j < 4; j++) ldsm4(bm[j], bbl + boff[j]);
#pragma unroll
            for (int j = 0; j < 4; j++) {
                mma16816(acc[0][2 * j],     ah0, bm[j][0], bm[j][1]);
                mma16816(acc[0][2 * j + 1], ah0, bm[j][2], bm[j][3]);
                mma16816(acc[1][2 * j],     ah1, bm[j][0], bm[j][1]);
                mma16816(acc[1][2 * j + 1], ah1, bm[j][2], bm[j][3]);
            }
        }

        if (s < 7) {
            STORE_A(buf ^ 1, af);
            CP_WAIT0();
            __syncthreads();
        }
        buf ^= 1;
    }

    // ---- epilogue: v . tanh(q + D) ---------------------------------------
    float part[2][2] = {{0.f, 0.f}, {0.f, 0.f}};
#pragma unroll
    for (int mg = 0; mg < 2; mg++) {
#pragma unroll
        for (int j = 0; j < 8; j++) {
            const int c = n0 + nw * 64 + j * 8 + 2 * (lid & 3);
            float2 q2 = *(const float2*)(g_q + b * 512 + c);
            float2 v2 = *(const float2*)(v + c);
            part[mg][0] += v2.x * fast_tanh(q2.x + acc[mg][j][0])
                         + v2.y * fast_tanh(q2.y + acc[mg][j][1]);
            part[mg][1] += v2.x * fast_tanh(q2.x + acc[mg][j][2])
                         + v2.y * fast_tanh(q2.y + acc[mg][j][3]);
        }
    }

    float* red = (float*)(sm + OFF_RED);   // [4 nw][128 rows]
    __syncthreads();
#pragma unroll
    for (int mg = 0; mg < 2; mg++)
#pragma unroll
        for (int hf = 0; hf < 2; hf++) {
            float p = part[mg][hf];
            p += __shfl_xor_sync(0xffffffffu, p, 1);
            p += __shfl_xor_sync(0xffffffffu, p, 2);
            if ((lid & 3) == 0)
                red[nw * 128 + mw * 32 + mg * 16 + hf * 8 + (lid >> 2)] = p;
        }
    __syncthreads();
    if (t < 128) {
        float p = red[t] + red[128 + t] + red[256 + t] + red[384 + t];
        atomicAdd(&g_scores[b * SS + mtile * 128 + t], p);
    }
}

// ---------------------------------------------------------------------------
// Softmax over S per batch row (applies mask here)
// ---------------------------------------------------------------------------
__global__ void softmax_kernel(const int* __restrict__ mask,
                               float* __restrict__ out_attn) {
    const int b = blockIdx.x;
    const int t = threadIdx.x;   // 256
    __shared__ float red[256];
    const float* sc = g_scores + b * SS;
    const int* mk = mask + b * SS;

    float vals[16];
    float m = -INFINITY;
#pragma unroll
    for (int i = 0; i < 16; i++) {
        int s = t + i * 256;
        vals[i] = (mk[s] != 0) ? -1e9f : sc[s];
        m = fmaxf(m, vals[i]);
    }
    red[t] = m;
    __syncthreads();
    for (int o = 128; o > 0; o >>= 1) {
        if (t < o) red[t] = fmaxf(red[t], red[t + o]);
        __syncthreads();
    }
    m = red[0];
    __syncthreads();

    float sum = 0.f;
#pragma unroll
    for (int i = 0; i < 16; i++) {
        vals[i] = expf(vals[i] - m);
        sum += vals[i];
    }
    red[t] = sum;
    __syncthreads();
    for (int o = 128; o > 0; o >>= 1) {
        if (t < o) red[t] += red[t + o];
        __syncthreads();
    }
    const float inv = 1.f / red[0];
#pragma unroll
    for (int i = 0; i < 16; i++)
        out_attn[b * SS + t + i * 256] = vals[i] * inv;
}

// ---------------------------------------------------------------------------
// ctx[b,e] = sum_s attn[b,s] * enc[b,s,e]
// grid (32 s-chunks, 32 b), 128 threads, float4/thread, 2 streams
// ---------------------------------------------------------------------------
__global__ void ctx_kernel(const float* __restrict__ enc_out,
                           const float* __restrict__ attn,
                           float* __restrict__ ctx) {
    const int b = blockIdx.y;
    const int sch = blockIdx.x;
    const int e4 = threadIdx.x * 4;
    const float* ap = attn + b * SS + sch * 128;
    const float* ep = enc_out + ((size_t)b * SS + (size_t)sch * 128) * 512 + e4;

    float4 acc0 = make_float4(0.f, 0.f, 0.f, 0.f);
    float4 acc1 = make_float4(0.f, 0.f, 0.f, 0.f);
#pragma unroll 8
    for (int s = 0; s < 128; s += 2) {
        float a0 = __ldg(&ap[s]);
        float a1 = __ldg(&ap[s + 1]);
        float4 x0 = *(const float4*)(ep + (size_t)s * 512);
        float4 x1 = *(const float4*)(ep + (size_t)(s + 1) * 512);
        acc0.x = fmaf(a0, x0.x, acc0.x);
        acc0.y = fmaf(a0, x0.y, acc0.y);
        acc0.z = fmaf(a0, x0.z, acc0.z);
        acc0.w = fmaf(a0, x0.w, acc0.w);
        acc1.x = fmaf(a1, x1.x, acc1.x);
        acc1.y = fmaf(a1, x1.y, acc1.y);
        acc1.z = fmaf(a1, x1.z, acc1.z);
        acc1.w = fmaf(a1, x1.w, acc1.w);
    }
    atomicAdd(&ctx[b * 512 + e4 + 0], acc0.x + acc1.x);
    atomicAdd(&ctx[b * 512 + e4 + 1], acc0.y + acc1.y);
    atomicAdd(&ctx[b * 512 + e4 + 2], acc0.z + acc1.z);
    atomicAdd(&ctx[b * 512 + e4 + 3], acc0.w + acc1.w);
}

// ---------------------------------------------------------------------------
extern "C" void kernel_launch(void* const* d_in, const int* in_sizes, int n_in,
                              void* d_out, int out_size) {
    const float* h    = (const float*)d_in[0];
    const float* enc  = (const float*)d_in[1];
    const int*   mask = (const int*)d_in[2];
    const float* W_h  = (const float*)d_in[3];
    const float* W_s  = (const float*)d_in[4];
    const float* v    = (const float*)d_in[5];

    float* out  = (float*)d_out;
    float* ctx  = out;                 // [32, 512]
    float* attn = out + BB * 512;      // [32, 4096]

    static int attr_done = 0;
    if (!attr_done) {
        cudaFuncSetAttribute(score_mma_kernel,
                             cudaFuncAttributeMaxDynamicSharedMemorySize, SMEM_DYN);
        attr_done = 1;
    }

    cudaMemsetAsync(ctx, 0, BB * 512 * sizeof(float));
    zero_scores_kernel<<<64, 512>>>();
    wsplit_kernel<<<512, 512>>>(W_s);
    query_kernel<<<BB, 512>>>(h, W_h);
    score_mma_kernel<<<dim3(32, 2, 32), 512, SMEM_DYN>>>(enc, v);
    softmax_kernel<<<BB, 256>>>(mask, attn);
    ctx_kernel<<<dim3(32, 32), 128>>>(enc, attn, ctx);
}

// round 6
// speedup vs baseline: 2.8456x; 1.0373x over previous
#include <cuda_runtime.h>
#include <cuda_bf16.h>
#include <math.h>
#include <stdint.h>

#define BB 32
#define SS 4096

// ---------------- device scratch ----------------
__device__ float g_q[BB * 512];
__device__ float g_scores[BB * SS];
__device__ __align__(16) unsigned short g_Wt_hi[512 * 512];  // W^T [a][e], bf16 hi
__device__ __align__(16) unsigned short g_Wt_lo[512 * 512];  // W^T [a][e], bf16 lo

// ---------------- smem layout (dynamic) ----------------
#define OFF_A    0        // 2 bufs x (hi 16KB + lo 16KB) = 64KB, rows 128 x 128B
#define OFF_B    65536    // 2 bufs x (hi 32KB + lo 32KB) = 128KB, rows 256 x 128B
#define OFF_RED  196608   // 4 x 128 f32
#define SMEM_DYN 198656

// ---------------- asm helpers ----------------
__device__ __forceinline__ uint32_t smem_to_u32(const void* p) {
    uint32_t a;
    asm("{ .reg .u64 t; cvta.to.shared.u64 t, %1; cvt.u32.u64 %0, t; }" : "=r"(a) : "l"(p));
    return a;
}
__device__ __forceinline__ void ldsm4(uint32_t* r, uint32_t addr) {
    asm volatile("ldmatrix.sync.aligned.m8n8.x4.shared.b16 {%0,%1,%2,%3}, [%4];"
                 : "=r"(r[0]), "=r"(r[1]), "=r"(r[2]), "=r"(r[3]) : "r"(addr));
}
__device__ __forceinline__ void mma16816(float* c, const uint32_t* a, uint32_t b0, uint32_t b1) {
    asm volatile("mma.sync.aligned.m16n8k16.row.col.f32.bf16.bf16.f32 "
                 "{%0,%1,%2,%3}, {%4,%5,%6,%7}, {%8,%9}, {%0,%1,%2,%3};"
                 : "+f"(c[0]), "+f"(c[1]), "+f"(c[2]), "+f"(c[3])
                 : "r"(a[0]), "r"(a[1]), "r"(a[2]), "r"(a[3]), "r"(b0), "r"(b1));
}
__device__ __forceinline__ void cp_async16(uint32_t dst, const void* src) {
    asm volatile("{ .reg .u64 g; cvta.to.global.u64 g, %1; "
                 "cp.async.cg.shared.global [%0], [g], 16; }"
                 :: "r"(dst), "l"(src) : "memory");
}
#define CP_COMMIT() asm volatile("cp.async.commit_group;" ::: "memory")
#define CP_WAIT0()  asm volatile("cp.async.wait_group 0;" ::: "memory")

// r = 1/(e^{2x}+1), where z = 2x*log2(e) precombined: z = fma(acc, C, qc).
// ex2 via MUFU; reciprocal via magic + 2 Newton (FMA pipe). ~10 instr, 1 MUFU.
#define TANH_C 2.885390081777927f
__device__ __forceinline__ float sig_rcp(float acc, float qc) {
    float z = fmaf(acc, TANH_C, qc);
    z = fminf(z, 126.0f);                 // keep e2 finite for the magic rcp
    float e2;
    asm("ex2.approx.f32 %0, %1;" : "=f"(e2) : "f"(z));
    float d = e2 + 1.0f;
    float y = __int_as_float(0x7EF311C3 - __float_as_int(d));
    y = y * fmaf(-d, y, 2.0f);
    y = y * fmaf(-d, y, 2.0f);
    return y;
}

// ---------------------------------------------------------------------------
// prep: wsplit (blocks 0..511) | query (512..543) | zero scores (544..607)
// ---------------------------------------------------------------------------
__global__ void prep_kernel(const float* __restrict__ W_s,
                            const float* __restrict__ h,
                            const float* __restrict__ W_h) {
    __shared__ float hs[512];
    const int bid = blockIdx.x;
    const int t = threadIdx.x;
    if (bid < 512) {                       // W split+transpose: e=bid, a=t
        float w = W_s[bid * 512 + t];
        uint32_t u = __float_as_uint(w);
        g_Wt_hi[(size_t)t * 512 + bid] = (unsigned short)(u >> 16);
        float lo = w - __uint_as_float(u & 0xffff0000u);
        __nv_bfloat16 lb = __float2bfloat16(lo);
        g_Wt_lo[(size_t)t * 512 + bid] = *(unsigned short*)&lb;
    } else if (bid < 544) {                // query GEMV: b=bid-512
        const int b = bid - 512;
        hs[t] = h[b * 512 + t];
        __syncthreads();
        float acc = 0.f;
#pragma unroll 8
        for (int e = 0; e < 512; e++)
            acc = fmaf(hs[e], W_h[e * 512 + t], acc);
        g_q[b * 512 + t] = acc;
    } else {                               // zero g_scores
        ((float4*)g_scores)[(bid - 544) * 512 + t] = make_float4(0.f, 0.f, 0.f, 0.f);
    }
}

// ---------------------------------------------------------------------------
// Score kernel: CTA = (m-tile 128 tok, n-tile 256 attn, b). 512 thr, 16 warps.
// Warp (mw, nw): tile m32 x n64. K streamed: 8 stages of 64. 3-pass bf16 split.
// ---------------------------------------------------------------------------
__global__ __launch_bounds__(512, 1)
void score_mma_kernel(const float* __restrict__ enc,
                      const float* __restrict__ v) {
    extern __shared__ __align__(128) char sm[];
    const uint32_t sb = smem_to_u32(sm);
    const int t = threadIdx.x;
    const int w = t >> 5, lid = t & 31;
    const int mw = w & 3, nw = w >> 2;
    const int mtile = blockIdx.x;          // 0..31
    const int n0 = blockIdx.y * 256;       // 0 or 256
    const int b = blockIdx.z;

    const float* encb = enc + ((size_t)b * SS + (size_t)mtile * 128) * 512;

    float acc[2][8][4];
#pragma unroll
    for (int mg = 0; mg < 2; mg++)
#pragma unroll
        for (int j = 0; j < 8; j++)
#pragma unroll
            for (int e = 0; e < 4; e++) acc[mg][j][e] = 0.f;

    const int am = t >> 2, akq = t & 3;

#define ISSUE_B(s_, buf_) do {                                                \
    const uint32_t bb = sb + OFF_B + (buf_) * 65536;                          \
    const int k0_ = (s_) * 64;                                                \
    _Pragma("unroll")                                                         \
    for (int i_ = 0; i_ < 8; i_++) {                                          \
        int idx_ = t + i_ * 512;                                              \
        int half_ = idx_ >> 11;                                               \
        int r_ = (idx_ >> 3) & 255;                                           \
        int cc_ = idx_ & 7;                                                   \
        const unsigned short* src_ =                                          \
            (half_ ? g_Wt_lo : g_Wt_hi) + (size_t)(n0 + r_) * 512 + k0_ + cc_ * 8; \
        cp_async16(bb + half_ * 32768 + r_ * 128 + ((cc_ ^ (r_ & 7)) << 4), src_); \
    } } while (0)

#define LOAD_A(s_, af_) do {                                                  \
    const float* p_ = encb + (size_t)am * 512 + (s_) * 64 + akq * 16;         \
    af_[0] = *(const float4*)(p_);                                            \
    af_[1] = *(const float4*)(p_ + 4);                                        \
    af_[2] = *(const float4*)(p_ + 8);                                        \
    af_[3] = *(const float4*)(p_ + 12);                                       \
    } while (0)

#define STORE_A(buf_, af_) do {                                               \
    char* ab_ = sm + OFF_A + (buf_) * 32768;                                  \
    _Pragma("unroll")                                                         \
    for (int c_ = 0; c_ < 2; c_++) {                                          \
        float4 f0 = af_[2 * c_], f1 = af_[2 * c_ + 1];                        \
        uint32_t x0 = __float_as_uint(f0.x), x1 = __float_as_uint(f0.y);      \
        uint32_t x2 = __float_as_uint(f0.z), x3 = __float_as_uint(f0.w);      \
        uint32_t x4 = __float_as_uint(f1.x), x5 = __float_as_uint(f1.y);      \
        uint32_t x6 = __float_as_uint(f1.z), x7 = __float_as_uint(f1.w);      \
        uint4 hv;                                                             \
        hv.x = __byte_perm(x0, x1, 0x7632);                                   \
        hv.y = __byte_perm(x2, x3, 0x7632);                                   \
        hv.z = __byte_perm(x4, x5, 0x7632);                                   \
        hv.w = __byte_perm(x6, x7, 0x7632);                                   \
        float l0 = f0.x - __uint_as_float(x0 & 0xffff0000u);                  \
        float l1 = f0.y - __uint_as_float(x1 & 0xffff0000u);                  \
        float l2 = f0.z - __uint_as_float(x2 & 0xffff0000u);                  \
        float l3 = f0.w - __uint_as_float(x3 & 0xffff0000u);                  \
        float l4 = f1.x - __uint_as_float(x4 & 0xffff0000u);                  \
        float l5 = f1.y - __uint_as_float(x5 & 0xffff0000u);                  \
        float l6 = f1.z - __uint_as_float(x6 & 0xffff0000u);                  \
        float l7 = f1.w - __uint_as_float(x7 & 0xffff0000u);                  \
        uint4 lv;                                                             \
        asm("cvt.rn.satfinite.bf16x2.f32 %0, %1, %2;" : "=r"(lv.x) : "f"(l1), "f"(l0)); \
        asm("cvt.rn.satfinite.bf16x2.f32 %0, %1, %2;" : "=r"(lv.y) : "f"(l3), "f"(l2)); \
        asm("cvt.rn.satfinite.bf16x2.f32 %0, %1, %2;" : "=r"(lv.z) : "f"(l5), "f"(l4)); \
        asm("cvt.rn.satfinite.bf16x2.f32 %0, %1, %2;" : "=r"(lv.w) : "f"(l7), "f"(l6)); \
        int cc_ = akq * 2 + c_;                                               \
        uint32_t off_ = am * 128 + ((cc_ ^ (am & 7)) << 4);                   \
        *(uint4*)(ab_ + off_) = hv;                                           \
        *(uint4*)(ab_ + 16384 + off_) = lv;                                   \
    } } while (0)

    const int rA = mw * 32 + ((lid >> 3) & 1) * 8 + (lid & 7);
    const int rAx = rA & 7;
    const int cAadd = lid >> 4;
    const int rB = nw * 64 + ((lid >> 4) & 1) * 8 + (lid & 7);
    const int cBadd = (lid >> 3) & 1;

    // ---- prologue --------------------------------------------------------
    ISSUE_B(0, 0);
    CP_COMMIT();
    {
        float4 af[4];
        LOAD_A(0, af);
        STORE_A(0, af);
    }
    CP_WAIT0();
    __syncthreads();

    int buf = 0;
#pragma unroll 1
    for (int s = 0; s < 8; s++) {
        float4 af[4];
        if (s < 7) {
            ISSUE_B(s + 1, buf ^ 1);
            CP_COMMIT();
            LOAD_A(s + 1, af);
        }

        const uint32_t abh = sb + OFF_A + buf * 32768;
        const uint32_t abl = abh + 16384;
        const uint32_t bbh = sb + OFF_B + buf * 65536;
        const uint32_t bbl = bbh + 32768;

#pragma unroll
        for (int kk = 0; kk < 4; kk++) {
            const int cA = kk * 2 + cAadd;
            const uint32_t a0off = (uint32_t)rA * 128 + (uint32_t)((cA ^ rAx) << 4);
            const uint32_t a1off = a0off + 16 * 128;
            const int cB = kk * 2 + cBadd;
            uint32_t boff[4];
            uint32_t bm[4][4];
#pragma unroll
            for (int j = 0; j < 4; j++) {
                int r = rB + j * 16;
                boff[j] = (uint32_t)r * 128 + (uint32_t)((cB ^ (r & 7)) << 4);
                ldsm4(bm[j], bbh + boff[j]);
            }
            uint32_t ah0[4], ah1[4], al[4];
            ldsm4(ah0, abh + a0off);
            ldsm4(ah1, abh + a1off);

#pragma unroll
            for (int j = 0; j < 4; j++) {
                mma16816(acc[0][2 * j],     ah0, bm[j][0], bm[j][1]);
                mma16816(acc[0][2 * j + 1], ah0, bm[j][2], bm[j][3]);
                mma16816(acc[1][2 * j],     ah1, bm[j][0], bm[j][1]);
                mma16816(acc[1][2 * j + 1], ah1, bm[j][2], bm[j][3]);
            }
            ldsm4(al, abl + a0off);
#pragma unroll
            for (int j = 0; j < 4; j++) {
                mma16816(acc[0][2 * j],     al, bm[j][0], bm[j][1]);
                mma16816(acc[0][2 * j + 1], al, bm[j][2], bm[j][3]);
            }
            ldsm4(al, abl + a1off);
#pragma unroll
            for (int j = 0; j < 4; j++) {
                mma16816(acc[1][2 * j],     al, bm[j][0], bm[j][1]);
                mma16816(acc[1][2 * j + 1], al, bm[j][2], bm[j][3]);
            }
#pragma unroll
            for (int j = 0; j < 4; j++) ldsm4(bm[j], bbl + boff[j]);
#pragma unroll
            for (int j = 0; j < 4; j++) {
                mma16816(acc[0][2 * j],     ah0, bm[j][0], bm[j][1]);
                mma16816(acc[0][2 * j + 1], ah0, bm[j][2], bm[j][3]);
                mma16816(acc[1][2 * j],     ah1, bm[j][0], bm[j][1]);
                mma16816(acc[1][2 * j + 1], ah1, bm[j][2], bm[j][3]);
            }
        }

        if (s < 7) {
            STORE_A(buf ^ 1, af);
            CP_WAIT0();
            __syncthreads();
        }
        buf ^= 1;
    }

    // ---- epilogue: score = Sv - 2 * sum(v * 1/(e^{2x}+1)) ----------------
    float qc[8][2], vv[8][2];
    float Sv = 0.f;
#pragma unroll
    for (int j = 0; j < 8; j++) {
        const int c = n0 + nw * 64 + j * 8 + 2 * (lid & 3);
        float2 q2 = *(const float2*)(g_q + b * 512 + c);
        float2 v2 = *(const float2*)(v + c);
        qc[j][0] = q2.x * TANH_C;
        qc[j][1] = q2.y * TANH_C;
        vv[j][0] = v2.x;
        vv[j][1] = v2.y;
        Sv += v2.x + v2.y;
    }

    float part[2][2] = {{0.f, 0.f}, {0.f, 0.f}};
#pragma unroll
    for (int mg = 0; mg < 2; mg++) {
#pragma unroll
        for (int j = 0; j < 8; j++) {
            part[mg][0] = fmaf(vv[j][0], sig_rcp(acc[mg][j][0], qc[j][0]), part[mg][0]);
            part[mg][0] = fmaf(vv[j][1], sig_rcp(acc[mg][j][1], qc[j][1]), part[mg][0]);
            part[mg][1] = fmaf(vv[j][0], sig_rcp(acc[mg][j][2], qc[j][0]), part[mg][1]);
            part[mg][1] = fmaf(vv[j][1], sig_rcp(acc[mg][j][3], qc[j][1]), part[mg][1]);
        }
    }

    float* red = (float*)(sm + OFF_RED);   // [4 nw][128 rows]
    __syncthreads();
#pragma unroll
    for (int mg = 0; mg < 2; mg++)
#pragma unroll
        for (int hf = 0; hf < 2; hf++) {
            float p = fmaf(-2.0f, part[mg][hf], Sv);
            p += __shfl_xor_sync(0xffffffffu, p, 1);
            p += __shfl_xor_sync(0xffffffffu, p, 2);
            if ((lid & 3) == 0)
                red[nw * 128 + mw * 32 + mg * 16 + hf * 8 + (lid >> 2)] = p;
        }
    __syncthreads();
    if (t < 128) {
        float p = red[t] + red[128 + t] + red[256 + t] + red[384 + t];
        atomicAdd(&g_scores[b * SS + mtile * 128 + t], p);
    }
}

// ---------------------------------------------------------------------------
// Softmax over S per batch row (applies mask here)
// ---------------------------------------------------------------------------
__global__ void softmax_kernel(const int* __restrict__ mask,
                               float* __restrict__ out_attn) {
    const int b = blockIdx.x;
    const int t = threadIdx.x;   // 256
    __shared__ float red[256];
    const float* sc = g_scores + b * SS;
    const int* mk = mask + b * SS;

    float vals[16];
    float m = -INFINITY;
#pragma unroll
    for (int i = 0; i < 16; i++) {
        int s = t + i * 256;
        vals[i] = (mk[s] != 0) ? -1e9f : sc[s];
        m = fmaxf(m, vals[i]);
    }
    red[t] = m;
    __syncthreads();
    for (int o = 128; o > 0; o >>= 1) {
        if (t < o) red[t] = fmaxf(red[t], red[t + o]);
        __syncthreads();
    }
    m = red[0];
    __syncthreads();

    float sum = 0.f;
#pragma unroll
    for (int i = 0; i < 16; i++) {
        vals[i] = expf(vals[i] - m);
        sum += vals[i];
    }
    red[t] = sum;
    __syncthreads();
    for (int o = 128; o > 0; o >>= 1) {
        if (t < o) red[t] += red[t + o];
        __syncthreads();
    }
    const float inv = 1.f / red[0];
#pragma unroll
    for (int i = 0; i < 16; i++)
        out_attn[b * SS + t + i * 256] = vals[i] * inv;
}

// ---------------------------------------------------------------------------
// ctx[b,e] = sum_s attn[b,s] * enc[b,s,e]
// ---------------------------------------------------------------------------
__global__ void ctx_kernel(const float* __restrict__ enc_out,
                           const float* __restrict__ attn,
                           float* __restrict__ ctx) {
    const int b = blockIdx.y;
    const int sch = blockIdx.x;
    const int e4 = threadIdx.x * 4;
    const float* ap = attn + b * SS + sch * 128;
    const float* ep = enc_out + ((size_t)b * SS + (size_t)sch * 128) * 512 + e4;

    float4 acc0 = make_float4(0.f, 0.f, 0.f, 0.f);
    float4 acc1 = make_float4(0.f, 0.f, 0.f, 0.f);
#pragma unroll 8
    for (int s = 0; s < 128; s += 2) {
        float a0 = __ldg(&ap[s]);
        float a1 = __ldg(&ap[s + 1]);
        float4 x0 = *(const float4*)(ep + (size_t)s * 512);
        float4 x1 = *(const float4*)(ep + (size_t)(s + 1) * 512);
        acc0.x = fmaf(a0, x0.x, acc0.x);
        acc0.y = fmaf(a0, x0.y, acc0.y);
        acc0.z = fmaf(a0, x0.z, acc0.z);
        acc0.w = fmaf(a0, x0.w, acc0.w);
        acc1.x = fmaf(a1, x1.x, acc1.x);
        acc1.y = fmaf(a1, x1.y, acc1.y);
        acc1.z = fmaf(a1, x1.z, acc1.z);
        acc1.w = fmaf(a1, x1.w, acc1.w);
    }
    atomicAdd(&ctx[b * 512 + e4 + 0], acc0.x + acc1.x);
    atomicAdd(&ctx[b * 512 + e4 + 1], acc0.y + acc1.y);
    atomicAdd(&ctx[b * 512 + e4 + 2], acc0.z + acc1.z);
    atomicAdd(&ctx[b * 512 + e4 + 3], acc0.w + acc1.w);
}

// ---------------------------------------------------------------------------
extern "C" void kernel_launch(void* const* d_in, const int* in_sizes, int n_in,
                              void* d_out, int out_size) {
    const float* h    = (const float*)d_in[0];
    const float* enc  = (const float*)d_in[1];
    const int*   mask = (const int*)d_in[2];
    const float* W_h  = (const float*)d_in[3];
    const float* W_s  = (const float*)d_in[4];
    const float* v    = (const float*)d_in[5];

    float* out  = (float*)d_out;
    float* ctx  = out;                 // [32, 512]
    float* attn = out + BB * 512;      // [32, 4096]

    static int attr_done = 0;
    if (!attr_done) {
        cudaFuncSetAttribute(score_mma_kernel,
                             cudaFuncAttributeMaxDynamicSharedMemorySize, SMEM_DYN);
        attr_done = 1;
    }

    cudaMemsetAsync(ctx, 0, BB * 512 * sizeof(float));
    prep_kernel<<<608, 512>>>(W_s, h, W_h);
    score_mma_kernel<<<dim3(32, 2, 32), 512, SMEM_DYN>>>(enc, v);
    softmax_kernel<<<BB, 256>>>(mask, attn);
    ctx_kernel<<<dim3(32, 32), 128>>>(enc, attn, ctx);
}

// round 7
// speedup vs baseline: 2.9769x; 1.0461x over previous
#include <cuda_runtime.h>
#include <cuda_bf16.h>
#include <math.h>
#include <stdint.h>

#define BB 32
#define SS 4096

// ---------------- device scratch ----------------
__device__ float g_q[BB * 512];
__device__ float g_scores[BB * SS];
__device__ __align__(16) unsigned short g_Wt_hi[512 * 512];  // W^T [a][e], bf16 hi
__device__ __align__(16) unsigned short g_Wt_lo[512 * 512];  // W^T [a][e], bf16 lo

// ---------------- smem layout (per CTA) ----------------
// A: 2 bufs x (hi 8KB + lo 8KB) = 32KB   rows: 64 x 128B
// B: 1 buf  x (hi 32KB + lo 32KB) = 64KB rows: 256 x 128B
#define OFF_A    0
#define OFF_B    32768
#define OFF_RED  98304    // 4 x 64 f32 = 1KB
#define SMEM_DYN 99328

// ---------------- asm helpers ----------------
__device__ __forceinline__ uint32_t smem_to_u32(const void* p) {
    uint32_t a;
    asm("{ .reg .u64 t; cvta.to.shared.u64 t, %1; cvt.u32.u64 %0, t; }" : "=r"(a) : "l"(p));
    return a;
}
__device__ __forceinline__ void ldsm4(uint32_t* r, uint32_t addr) {
    asm volatile("ldmatrix.sync.aligned.m8n8.x4.shared.b16 {%0,%1,%2,%3}, [%4];"
                 : "=r"(r[0]), "=r"(r[1]), "=r"(r[2]), "=r"(r[3]) : "r"(addr));
}
__device__ __forceinline__ void mma16816(float* c, const uint32_t* a, uint32_t b0, uint32_t b1) {
    asm volatile("mma.sync.aligned.m16n8k16.row.col.f32.bf16.bf16.f32 "
                 "{%0,%1,%2,%3}, {%4,%5,%6,%7}, {%8,%9}, {%0,%1,%2,%3};"
                 : "+f"(c[0]), "+f"(c[1]), "+f"(c[2]), "+f"(c[3])
                 : "r"(a[0]), "r"(a[1]), "r"(a[2]), "r"(a[3]), "r"(b0), "r"(b1));
}
__device__ __forceinline__ void cp_async16(uint32_t dst, const void* src) {
    asm volatile("{ .reg .u64 g; cvta.to.global.u64 g, %1; "
                 "cp.async.cg.shared.global [%0], [g], 16; }"
                 :: "r"(dst), "l"(src) : "memory");
}
#define CP_COMMIT() asm volatile("cp.async.commit_group;" ::: "memory")
#define CP_WAIT0()  asm volatile("cp.async.wait_group 0;" ::: "memory")

// r = 1/(e^{2x}+1); z = fma(acc, C, qc). ex2 via MUFU, rcp via magic+2 Newton.
#define TANH_C 2.885390081777927f
__device__ __forceinline__ float sig_rcp(float acc, float qc) {
    float z = fmaf(acc, TANH_C, qc);
    z = fminf(z, 126.0f);
    float e2;
    asm("ex2.approx.f32 %0, %1;" : "=f"(e2) : "f"(z));
    float d = e2 + 1.0f;
    float y = __int_as_float(0x7EF311C3 - __float_as_int(d));
    y = y * fmaf(-d, y, 2.0f);
    y = y * fmaf(-d, y, 2.0f);
    return y;
}

// ---------------------------------------------------------------------------
// prep: wsplit (blocks 0..511) | query (512..543) | zero scores (544..607)
// ---------------------------------------------------------------------------
__global__ void prep_kernel(const float* __restrict__ W_s,
                            const float* __restrict__ h,
                            const float* __restrict__ W_h) {
    __shared__ float hs[512];
    const int bid = blockIdx.x;
    const int t = threadIdx.x;
    if (bid < 512) {
        float w = W_s[bid * 512 + t];
        uint32_t u = __float_as_uint(w);
        g_Wt_hi[(size_t)t * 512 + bid] = (unsigned short)(u >> 16);
        float lo = w - __uint_as_float(u & 0xffff0000u);
        __nv_bfloat16 lb = __float2bfloat16(lo);
        g_Wt_lo[(size_t)t * 512 + bid] = *(unsigned short*)&lb;
    } else if (bid < 544) {
        const int b = bid - 512;
        hs[t] = h[b * 512 + t];
        __syncthreads();
        float acc = 0.f;
#pragma unroll 8
        for (int e = 0; e < 512; e++)
            acc = fmaf(hs[e], W_h[e * 512 + t], acc);
        g_q[b * 512 + t] = acc;
    } else {
        ((float4*)g_scores)[(bid - 544) * 512 + t] = make_float4(0.f, 0.f, 0.f, 0.f);
    }
}

// ---------------------------------------------------------------------------
// Score kernel: CTA = (m-tile 64 tok, n-tile 256 attn, b). 256 thr, 8 warps,
// 2 CTAs/SM. Warp (mw=w&1, nw=w>>1): tile m32 x n64. K: 8 stages of 64.
// A double-buffered (fp32->bf16 hi/lo in-kernel), B single-buffered cp.async.
// ---------------------------------------------------------------------------
__global__ __launch_bounds__(256, 2)
void score_mma_kernel(const float* __restrict__ enc,
                      const float* __restrict__ v) {
    extern __shared__ __align__(128) char sm[];
    const uint32_t sb = smem_to_u32(sm);
    const int t = threadIdx.x;
    const int w = t >> 5, lid = t & 31;
    const int mw = w & 1, nw = w >> 1;
    const int mtile = blockIdx.x;          // 0..63
    const int n0 = blockIdx.y * 256;       // 0 or 256
    const int b = blockIdx.z;

    const float* encb = enc + ((size_t)b * SS + (size_t)mtile * 64) * 512;

    float acc[2][8][4];
#pragma unroll
    for (int mg = 0; mg < 2; mg++)
#pragma unroll
        for (int j = 0; j < 8; j++)
#pragma unroll
            for (int e = 0; e < 4; e++) acc[mg][j][e] = 0.f;

    const int am = t >> 2, akq = t & 3;    // A roles: row 0..63, quad 0..3

// B stage: 64KB = 4096 chunks of 16B; 16 per thread
#define ISSUE_B(s_) do {                                                      \
    const uint32_t bb = sb + OFF_B;                                           \
    const int k0_ = (s_) * 64;                                                \
    _Pragma("unroll")                                                         \
    for (int i_ = 0; i_ < 16; i_++) {                                         \
        int idx_ = t + i_ * 256;                                              \
        int half_ = idx_ >> 11;                                               \
        int r_ = (idx_ >> 3) & 255;                                           \
        int cc_ = idx_ & 7;                                                   \
        const unsigned short* src_ =                                          \
            (half_ ? g_Wt_lo : g_Wt_hi) + (size_t)(n0 + r_) * 512 + k0_ + cc_ * 8; \
        cp_async16(bb + half_ * 32768 + r_ * 128 + ((cc_ ^ (r_ & 7)) << 4), src_); \
    } } while (0)

#define LOAD_A(s_, af_) do {                                                  \
    const float* p_ = encb + (size_t)am * 512 + (s_) * 64 + akq * 16;         \
    af_[0] = *(const float4*)(p_);                                            \
    af_[1] = *(const float4*)(p_ + 4);                                        \
    af_[2] = *(const float4*)(p_ + 8);                                        \
    af_[3] = *(const float4*)(p_ + 12);                                       \
    } while (0)

#define STORE_A(buf_, af_) do {                                               \
    char* ab_ = sm + OFF_A + (buf_) * 16384;                                  \
    _Pragma("unroll")                                                         \
    for (int c_ = 0; c_ < 2; c_++) {                                          \
        float4 f0 = af_[2 * c_], f1 = af_[2 * c_ + 1];                        \
        uint32_t x0 = __float_as_uint(f0.x), x1 = __float_as_uint(f0.y);      \
        uint32_t x2 = __float_as_uint(f0.z), x3 = __float_as_uint(f0.w);      \
        uint32_t x4 = __float_as_uint(f1.x), x5 = __float_as_uint(f1.y);      \
        uint32_t x6 = __float_as_uint(f1.z), x7 = __float_as_uint(f1.w);      \
        uint4 hv;                                                             \
        hv.x = __byte_perm(x0, x1, 0x7632);                                   \
        hv.y = __byte_perm(x2, x3, 0x7632);                                   \
        hv.z = __byte_perm(x4, x5, 0x7632);                                   \
        hv.w = __byte_perm(x6, x7, 0x7632);                                   \
        float l0 = f0.x - __uint_as_float(x0 & 0xffff0000u);                  \
        float l1 = f0.y - __uint_as_float(x1 & 0xffff0000u);                  \
        float l2 = f0.z - __uint_as_float(x2 & 0xffff0000u);                  \
        float l3 = f0.w - __uint_as_float(x3 & 0xffff0000u);                  \
        float l4 = f1.x - __uint_as_float(x4 & 0xffff0000u);                  \
        float l5 = f1.y - __uint_as_float(x5 & 0xffff0000u);                  \
        float l6 = f1.z - __uint_as_float(x6 & 0xffff0000u);                  \
        float l7 = f1.w - __uint_as_float(x7 & 0xffff0000u);                  \
        uint4 lv;                                                             \
        asm("cvt.rn.satfinite.bf16x2.f32 %0, %1, %2;" : "=r"(lv.x) : "f"(l1), "f"(l0)); \
        asm("cvt.rn.satfinite.bf16x2.f32 %0, %1, %2;" : "=r"(lv.y) : "f"(l3), "f"(l2)); \
        asm("cvt.rn.satfinite.bf16x2.f32 %0, %1, %2;" : "=r"(lv.z) : "f"(l5), "f"(l4)); \
        asm("cvt.rn.satfinite.bf16x2.f32 %0, %1, %2;" : "=r"(lv.w) : "f"(l7), "f"(l6)); \
        int cc_ = akq * 2 + c_;                                               \
        uint32_t off_ = am * 128 + ((cc_ ^ (am & 7)) << 4);                   \
        *(uint4*)(ab_ + off_) = hv;                                           \
        *(uint4*)(ab_ + 8192 + off_) = lv;                                    \
    } } while (0)

    const int rA = mw * 32 + ((lid >> 3) & 1) * 8 + (lid & 7);  // 0..47
    const int rAx = rA & 7;
    const int cAadd = lid >> 4;
    const int rB = nw * 64 + ((lid >> 4) & 1) * 8 + (lid & 7);
    const int cBadd = (lid >> 3) & 1;

    // ---- prologue: stage 0 ------------------------------------------------
    ISSUE_B(0);
    CP_COMMIT();
    {
        float4 af[4];
        LOAD_A(0, af);
        STORE_A(0, af);
    }
    CP_WAIT0();
    __syncthreads();

#pragma unroll 1
    for (int s = 0; s < 8; s++) {
        const int buf = s & 1;
        float4 af[4];
        if (s < 7) LOAD_A(s + 1, af);    // LDG early; latency hidden by MMAs

        const uint32_t abh = sb + OFF_A + buf * 16384;
        const uint32_t abl = abh + 8192;
        const uint32_t bbh = sb + OFF_B;
        const uint32_t bbl = bbh + 32768;

#pragma unroll
        for (int kk = 0; kk < 4; kk++) {
            const int cA = kk * 2 + cAadd;
            const uint32_t a0off = (uint32_t)rA * 128 + (uint32_t)((cA ^ rAx) << 4);
            const uint32_t a1off = a0off + 16 * 128;
            const int cB = kk * 2 + cBadd;
            uint32_t boff[4];
            uint32_t bm[4][4];
#pragma unroll
            for (int j = 0; j < 4; j++) {
                int r = rB + j * 16;
                boff[j] = (uint32_t)r * 128 + (uint32_t)((cB ^ (r & 7)) << 4);
                ldsm4(bm[j], bbh + boff[j]);
            }
            uint32_t ah0[4], ah1[4], al[4];
            ldsm4(ah0, abh + a0off);
            ldsm4(ah1, abh + a1off);

#pragma unroll
            for (int j = 0; j < 4; j++) {
                mma16816(acc[0][2 * j],     ah0, bm[j][0], bm[j][1]);
                mma16816(acc[0][2 * j + 1], ah0, bm[j][2], bm[j][3]);
                mma16816(acc[1][2 * j],     ah1, bm[j][0], bm[j][1]);
                mma16816(acc[1][2 * j + 1], ah1, bm[j][2], bm[j][3]);
            }
            ldsm4(al, abl + a0off);
#pragma unroll
            for (int j = 0; j < 4; j++) {
                mma16816(acc[0][2 * j],     al, bm[j][0], bm[j][1]);
                mma16816(acc[0][2 * j + 1], al, bm[j][2], bm[j][3]);
            }
            ldsm4(al, abl + a1off);
#pragma unroll
            for (int j = 0; j < 4; j++) {
                mma16816(acc[1][2 * j],     al, bm[j][0], bm[j][1]);
                mma16816(acc[1][2 * j + 1], al, bm[j][2], bm[j][3]);
            }
#pragma unroll
            for (int j = 0; j < 4; j++) ldsm4(bm[j], bbl + boff[j]);
#pragma unroll
            for (int j = 0; j < 4; j++) {
                mma16816(acc[0][2 * j],     ah0, bm[j][0], bm[j][1]);
                mma16816(acc[0][2 * j + 1], ah0, bm[j][2], bm[j][3]);
                mma16816(acc[1][2 * j],     ah1, bm[j][0], bm[j][1]);
                mma16816(acc[1][2 * j + 1], ah1, bm[j][2], bm[j][3]);
            }
        }

        if (s < 7) {
            STORE_A(buf ^ 1, af);        // other A buffer: safe during compute
            __syncthreads();             // all warps done reading B(s)
            ISSUE_B(s + 1);
            CP_COMMIT();
            CP_WAIT0();
            __syncthreads();             // B(s+1) visible
        }
    }

    // ---- epilogue: score = Sv - 2 * sum(v * 1/(e^{2x}+1)) ----------------
    float qc[8][2], vv[8][2];
    float Sv = 0.f;
#pragma unroll
    for (int j = 0; j < 8; j++) {
        const int c = n0 + nw * 64 + j * 8 + 2 * (lid & 3);
        float2 q2 = *(const float2*)(g_q + b * 512 + c);
        float2 v2 = *(const float2*)(v + c);
        qc[j][0] = q2.x * TANH_C;
        qc[j][1] = q2.y * TANH_C;
        vv[j][0] = v2.x;
        vv[j][1] = v2.y;
        Sv += v2.x + v2.y;
    }

    float part[2][2] = {{0.f, 0.f}, {0.f, 0.f}};
#pragma unroll
    for (int mg = 0; mg < 2; mg++) {
#pragma unroll
        for (int j = 0; j < 8; j++) {
            part[mg][0] = fmaf(vv[j][0], sig_rcp(acc[mg][j][0], qc[j][0]), part[mg][0]);
            part[mg][0] = fmaf(vv[j][1], sig_rcp(acc[mg][j][1], qc[j][1]), part[mg][0]);
            part[mg][1] = fmaf(vv[j][0], sig_rcp(acc[mg][j][2], qc[j][0]), part[mg][1]);
            part[mg][1] = fmaf(vv[j][1], sig_rcp(acc[mg][j][3], qc[j][1]), part[mg][1]);
        }
    }

    float* red = (float*)(sm + OFF_RED);   // [4 nw][64 rows]
    __syncthreads();
#pragma unroll
    for (int mg = 0; mg < 2; mg++)
#pragma unroll
        for (int hf = 0; hf < 2; hf++) {
            float p = fmaf(-2.0f, part[mg][hf], Sv);
            p += __shfl_xor_sync(0xffffffffu, p, 1);
            p += __shfl_xor_sync(0xffffffffu, p, 2);
            if ((lid & 3) == 0)
                red[nw * 64 + mw * 32 + mg * 16 + hf * 8 + (lid >> 2)] = p;
        }
    __syncthreads();
    if (t < 64) {
        float p = red[t] + red[64 + t] + red[128 + t] + red[192 + t];
        atomicAdd(&g_scores[b * SS + mtile * 64 + t], p);
    }
}

// ---------------------------------------------------------------------------
// Softmax over S per batch row (applies mask here)
// ---------------------------------------------------------------------------
__global__ void softmax_kernel(const int* __restrict__ mask,
                               float* __restrict__ out_attn) {
    const int b = blockIdx.x;
    const int t = threadIdx.x;   // 256
    __shared__ float red[256];
    const float* sc = g_scores + b * SS;
    const int* mk = mask + b * SS;

    float vals[16];
    float m = -INFINITY;
#pragma unroll
    for (int i = 0; i < 16; i++) {
        int s = t + i * 256;
        vals[i] = (mk[s] != 0) ? -1e9f : sc[s];
        m = fmaxf(m, vals[i]);
    }
    red[t] = m;
    __syncthreads();
    for (int o = 128; o > 0; o >>= 1) {
        if (t < o) red[t] = fmaxf(red[t], red[t + o]);
        __syncthreads();
    }
    m = red[0];
    __syncthreads();

    float sum = 0.f;
#pragma unroll
    for (int i = 0; i < 16; i++) {
        vals[i] = expf(vals[i] - m);
        sum += vals[i];
    }
    red[t] = sum;
    __syncthreads();
    for (int o = 128; o > 0; o >>= 1) {
        if (t < o) red[t] += red[t + o];
        __syncthreads();
    }
    const float inv = 1.f / red[0];
#pragma unroll
    for (int i = 0; i < 16; i++)
        out_attn[b * SS + t + i * 256] = vals[i] * inv;
}

// ---------------------------------------------------------------------------
// ctx[b,e] = sum_s attn[b,s] * enc[b,s,e]
// ---------------------------------------------------------------------------
__global__ void ctx_kernel(const float* __restrict__ enc_out,
                           const float* __restrict__ attn,
                           float* __restrict__ ctx) {
    const int b = blockIdx.y;
    const int sch = blockIdx.x;
    const int e4 = threadIdx.x * 4;
    const float* ap = attn + b * SS + sch * 128;
    const float* ep = enc_out + ((size_t)b * SS + (size_t)sch * 128) * 512 + e4;

    float4 acc0 = make_float4(0.f, 0.f, 0.f, 0.f);
    float4 acc1 = make_float4(0.f, 0.f, 0.f, 0.f);
#pragma unroll 8
    for (int s = 0; s < 128; s += 2) {
        float a0 = __ldg(&ap[s]);
        float a1 = __ldg(&ap[s + 1]);
        float4 x0 = *(const float4*)(ep + (size_t)s * 512);
        float4 x1 = *(const float4*)(ep + (size_t)(s + 1) * 512);
        acc0.x = fmaf(a0, x0.x, acc0.x);
        acc0.y = fmaf(a0, x0.y, acc0.y);
        acc0.z = fmaf(a0, x0.z, acc0.z);
        acc0.w = fmaf(a0, x0.w, acc0.w);
        acc1.x = fmaf(a1, x1.x, acc1.x);
        acc1.y = fmaf(a1, x1.y, acc1.y);
        acc1.z = fmaf(a1, x1.z, acc1.z);
        acc1.w = fmaf(a1, x1.w, acc1.w);
    }
    atomicAdd(&ctx[b * 512 + e4 + 0], acc0.x + acc1.x);
    atomicAdd(&ctx[b * 512 + e4 + 1], acc0.y + acc1.y);
    atomicAdd(&ctx[b * 512 + e4 + 2], acc0.z + acc1.z);
    atomicAdd(&ctx[b * 512 + e4 + 3], acc0.w + acc1.w);
}

// ---------------------------------------------------------------------------
extern "C" void kernel_launch(void* const* d_in, const int* in_sizes, int n_in,
                              void* d_out, int out_size) {
    const float* h    = (const float*)d_in[0];
    const float* enc  = (const float*)d_in[1];
    const int*   mask = (const int*)d_in[2];
    const float* W_h  = (const float*)d_in[3];
    const float* W_s  = (const float*)d_in[4];
    const float* v    = (const float*)d_in[5];

    float* out  = (float*)d_out;
    float* ctx  = out;                 // [32, 512]
    float* attn = out + BB * 512;      // [32, 4096]

    static int attr_done = 0;
    if (!attr_done) {
        cudaFuncSetAttribute(score_mma_kernel,
                             cudaFuncAttributeMaxDynamicSharedMemorySize, SMEM_DYN);
        attr_done = 1;
    }

    cudaMemsetAsync(ctx, 0, BB * 512 * sizeof(float));
    prep_kernel<<<608, 512>>>(W_s, h, W_h);
    score_mma_kernel<<<dim3(64, 2, 32), 256, SMEM_DYN>>>(enc, v);
    softmax_kernel<<<BB, 256>>>(mask, attn);
    ctx_kernel<<<dim3(32, 32), 128>>>(enc, attn, ctx);
}